// round 3
// baseline (speedup 1.0000x reference)
#include <cuda_runtime.h>
#include <math.h>

// VIN: B=128 images, 64x64, L_I=2, L_H=150 (collapsed analytically), L_Q=10, K=50.
// One CTA per image; everything resident in SMEM; VI loop inside the kernel.

#define NT   256
#define PADW 68                      // padded row width for 66-row halo arrays
#define R_OFF    0                   // r buffer, also reused as v "next" buffer
#define VA_OFF   4488                // 66*68
#define QR_OFF   (2*4488)
#define WEFF_OFF (QR_OFF + 10*4096)
#define SMEM_FLOATS (WEFF_OFF + 20)  // 49956 floats = 199824 bytes

__global__ __launch_bounds__(NT, 1)
void vin_kernel(const float* __restrict__ X,
                const float* __restrict__ h_w,
                const float* __restrict__ h_b,
                const float* __restrict__ r_w,
                const float* __restrict__ q_w,
                const float* __restrict__ w,
                const float* __restrict__ fc_w,
                const void*  S1v, const void* S2v,
                const void*  kv,
                float* __restrict__ out)
{
    extern __shared__ float sm[];
    float* r_s  = sm + R_OFF;    // 66x68, halo zero; later reused as v-next
    float* va_s = sm + VA_OFF;   // 66x68, halo zero
    float* qr_s = sm + QR_OFF;   // 10 x 64 x 64
    float* weff = sm + WEFF_OFF; // [0..17] W_eff, [18] b_eff
    __shared__ int wzero_s, s64_s, kval_s;

    const int b = blockIdx.x;
    const int t = threadIdx.x;

    // Zero r and v buffers (establishes zero halos for SAME padding).
    for (int idx = t; idx < 2*4488; idx += NT) sm[idx] = 0.0f;

    // Collapse the 150-channel hidden layer:
    //   W_eff[c,ky,kx] = sum_h r_w[h] * h_w[h,c,ky,kx],  b_eff = sum_h r_w[h]*h_b[h]
    if (t < 18) {
        float acc = 0.0f;
        for (int h = 0; h < 150; h++) acc += r_w[h] * h_w[h*18 + t];
        weff[t] = acc;
    } else if (t == 18) {
        float acc = 0.0f;
        for (int h = 0; h < 150; h++) acc += r_w[h] * h_b[h];
        weff[18] = acc;
    } else if (t == 19) {
        // Is the v-branch weight tensor identically zero? (it is, by construction)
        int z = 1;
        for (int i = 0; i < 90; i++) if (w[i] != 0.0f) { z = 0; break; }
        wzero_s = z;
    } else if (t == 20) {
        // Detect int64 vs int32 layout of S1/S2: int64 little-endian has all
        // high words == 0 (values are in [0,64)). 64 odd-position int32 reads
        // are in-bounds for both layouts.
        const int* p = (const int*)S1v;
        int f = 1;
        for (int i = 0; i < 64; i++) if (p[2*i + 1] != 0) { f = 0; break; }
        s64_s = f;
    } else if (t == 21) {
        kval_s = kv ? ((const int*)kv)[0] : 50;   // LE: low word is the value either width
    }
    __syncthreads();

    // ---- r = conv3x3(X, W_eff) + b_eff  (SAME, zero pad) ----
    {
        float we[18];
        #pragma unroll
        for (int i2 = 0; i2 < 18; i2++) we[i2] = weff[i2];
        const float beff = weff[18];
        const float* X0 = X + (size_t)b * 2 * 4096;
        #pragma unroll 1
        for (int s = 0; s < 16; s++) {
            int p = s*NT + t;
            int i = p >> 6, j = p & 63;
            float acc = beff;
            #pragma unroll
            for (int c = 0; c < 2; c++) {
                const float* Xc = X0 + c*4096;
                #pragma unroll
                for (int dy = 0; dy < 3; dy++) {
                    int ii = i + dy - 1;
                    #pragma unroll
                    for (int dx = 0; dx < 3; dx++) {
                        int jj = j + dx - 1;
                        if (ii >= 0 && ii < 64 && jj >= 0 && jj < 64)
                            acc += we[c*9 + dy*3 + dx] * Xc[ii*64 + jj];
                    }
                }
            }
            r_s[(i+1)*PADW + (j+1)] = acc;
        }
    }
    __syncthreads();

    // ---- qr[a] = conv3x3(r, q_w[a]) (iteration-invariant), v0 = max_a qr ----
    {
        float qw[90];
        #pragma unroll
        for (int i2 = 0; i2 < 90; i2++) qw[i2] = q_w[i2];
        #pragma unroll 1
        for (int s = 0; s < 16; s++) {
            int p = s*NT + t;
            int i = p >> 6, j = p & 63;
            float n[9];
            #pragma unroll
            for (int dy = 0; dy < 3; dy++)
                #pragma unroll
                for (int dx = 0; dx < 3; dx++)
                    n[dy*3 + dx] = r_s[(i+dy)*PADW + (j+dx)];
            float vmax = -3.402823466e38f;
            #pragma unroll
            for (int a = 0; a < 10; a++) {
                float acc = 0.0f;
                #pragma unroll
                for (int m = 0; m < 9; m++) acc += qw[a*9 + m] * n[m];
                qr_s[a*4096 + p] = acc;
                vmax = fmaxf(vmax, acc);
            }
            va_s[(i+1)*PADW + (j+1)] = vmax;
        }
    }
    __syncthreads();

    // ---- Value-iteration loop: v <- max_a ( qr[a] + conv3x3(v, w[a]) ) ----
    float ww[90];
    #pragma unroll
    for (int i2 = 0; i2 < 90; i2++) ww[i2] = w[i2];

    float* vcur = va_s;
    float* vnxt = r_s;   // r no longer needed; halo already zero

    if (!wzero_s) {
        const int K = kval_s;
        for (int it = 0; it < K - 1; it++) {
            #pragma unroll 1
            for (int s = 0; s < 16; s++) {
                int p = s*NT + t;
                int i = p >> 6, j = p & 63;
                float n[9];
                #pragma unroll
                for (int dy = 0; dy < 3; dy++)
                    #pragma unroll
                    for (int dx = 0; dx < 3; dx++)
                        n[dy*3 + dx] = vcur[(i+dy)*PADW + (j+dx)];
                float vmax = -3.402823466e38f;
                #pragma unroll
                for (int a = 0; a < 10; a++) {
                    float acc = qr_s[a*4096 + p];
                    #pragma unroll
                    for (int m = 0; m < 9; m++) acc += ww[a*9 + m] * n[m];
                    vmax = fmaxf(vmax, acc);
                }
                vnxt[(i+1)*PADW + (j+1)] = vmax;
            }
            float* tmp = vcur; vcur = vnxt; vnxt = tmp;
            __syncthreads();
        }
    }

    __syncthreads();

    // ---- Final step at the gather pixel only + FC + softmax ----
    if (t == 0) {
        int si, sj;
        if (s64_s) {
            si = (int)((const long long*)S1v)[b];
            sj = (int)((const long long*)S2v)[b];
        } else {
            si = ((const int*)S1v)[b];
            sj = ((const int*)S2v)[b];
        }
        float qout[10];
        #pragma unroll
        for (int a = 0; a < 10; a++) {
            float acc = qr_s[a*4096 + si*64 + sj];
            #pragma unroll
            for (int dy = 0; dy < 3; dy++)
                #pragma unroll
                for (int dx = 0; dx < 3; dx++)
                    acc += ww[a*9 + dy*3 + dx] * vcur[(si+dy)*PADW + (sj+dx)];
            qout[a] = acc;
        }
        float logits[8];
        float lmax = -3.402823466e38f;
        #pragma unroll
        for (int jj = 0; jj < 8; jj++) {
            float acc = 0.0f;
            #pragma unroll
            for (int a = 0; a < 10; a++) acc += qout[a] * fc_w[jj*10 + a];
            logits[jj] = acc;
            lmax = fmaxf(lmax, acc);
        }
        float ex[8];
        float den = 0.0f;
        #pragma unroll
        for (int jj = 0; jj < 8; jj++) { ex[jj] = expf(logits[jj] - lmax); den += ex[jj]; }
        float inv = 1.0f / den;
        #pragma unroll
        for (int jj = 0; jj < 8; jj++) {
            out[b*8 + jj]           = logits[jj];      // logits block: [0, 1024)
            out[128*8 + b*8 + jj]   = ex[jj] * inv;    // probs block:  [1024, 2048)
        }
    }
}

extern "C" void kernel_launch(void* const* d_in, const int* in_sizes, int n_in,
                              void* d_out, int out_size)
{
    (void)in_sizes; (void)out_size;
    const float* X    = (const float*)d_in[0];
    const float* h_w  = (const float*)d_in[1];
    const float* h_b  = (const float*)d_in[2];
    const float* r_w  = (const float*)d_in[3];
    const float* q_w  = (const float*)d_in[4];
    const float* w    = (const float*)d_in[5];
    const float* fc_w = (const float*)d_in[6];
    const void*  S1   = d_in[7];
    const void*  S2   = d_in[8];
    // d_in[9], d_in[10] = O1, O2: unused by the reference computation
    const void*  kv   = (n_in > 11) ? d_in[11] : nullptr;

    const size_t smem = SMEM_FLOATS * sizeof(float);   // 199824 bytes
    cudaFuncSetAttribute(vin_kernel, cudaFuncAttributeMaxDynamicSharedMemorySize, (int)smem);
    vin_kernel<<<128, NT, smem>>>(X, h_w, h_b, r_w, q_w, w, fc_w, S1, S2, kv,
                                  (float*)d_out);
}

// round 4
// speedup vs baseline: 2.6103x; 2.6103x over previous
#include <cuda_runtime.h>
#include <math.h>

// VIN: B=128 images, 64x64, L_I=2, L_H=150 (collapsed analytically), L_Q=10, K=50.
// One CTA per image.
//
// Fast path (w == 0, verified at runtime): the VI scan is the identity and v
// never reaches the output, so the answer per image is qr = conv(conv(X,W_eff),q_w)
// at the single gather pixel -> O(1) work: 5x5 X patch, 3x3 r patch, 10 q values.
// Slow path (w != 0): full in-SMEM value iteration (previous round's algorithm).

#define NT   256
#define PADW 68
#define R_OFF    0
#define VA_OFF   4488                // 66*68
#define QR_OFF   (2*4488)
#define SMEM_FLOATS (QR_OFF + 10*4096)   // 49936 floats (dynamic, slow path only)

__global__ __launch_bounds__(NT, 1)
void vin_kernel(const float* __restrict__ X,
                const float* __restrict__ h_w,
                const float* __restrict__ h_b,
                const float* __restrict__ r_w,
                const float* __restrict__ q_w,
                const float* __restrict__ w,
                const float* __restrict__ fc_w,
                const void*  S1v, const void* S2v,
                const void*  kv,
                float* __restrict__ out)
{
    extern __shared__ float sm[];                  // slow path scratch only
    __shared__ float ws[90];                       // w
    __shared__ float qw_s[90];                     // q_w
    __shared__ float fc_s[80];                     // fc_w
    __shared__ float weff_s[19];                   // collapsed hidden layer (+bias)
    __shared__ float partial_s[152];               // weff partial sums
    __shared__ float xs_s[50];                     // 2ch x 5x5 X patch (fast path)
    __shared__ float rp_s[9];                      // 3x3 r patch (fast path)
    __shared__ float qv_s[10];                     // q at gather pixel (fast path)
    __shared__ int wnz_s, s64_s, kval_s;
    __shared__ int scand_s[4];                     // S1_i32, S1_i64lo, S2_i32, S2_i64lo

    const int b = blockIdx.x;
    const int t = threadIdx.x;

    if (t == 0) { wnz_s = 0; s64_s = 1; }
    __syncthreads();

    // ---- Phase 0: all independent global loads in flight at once ----
    if (t < 90) {
        float v = w[t];
        ws[t] = v;
        if (v != 0.0f) atomicOr(&wnz_s, 1);
    } else if (t < 154) {
        // int64-vs-int32 layout probe: int64 LE has all high words == 0
        // (values in [0,64)). 64 odd-position int32 reads, in-bounds either way.
        int i = t - 90;
        if (((const int*)S1v)[2*i + 1] != 0) atomicExch(&s64_s, 0);
    } else if (t < 244) {
        qw_s[t - 154] = q_w[t - 154];
    } else if (t == 254) {
        kval_s = kv ? ((const int*)kv)[0] : 50;    // LE low word works either width
    } else if (t == 255) {
        scand_s[0] = ((const int*)S1v)[b];
        scand_s[1] = (int)((const long long*)S1v)[b];
        scand_s[2] = ((const int*)S2v)[b];
        scand_s[3] = (int)((const long long*)S2v)[b];
    }

    // W_eff partials: 19 outputs x 8 chunks of <=19 h-values each (parallel
    // with phase 0 — no shared inputs needed).
    if (t < 152) {
        int o = t >> 3, c = t & 7;
        int h0 = c * 19, h1 = (h0 + 19 < 150) ? h0 + 19 : 150;
        float acc = 0.0f;
        if (o < 18) { for (int h = h0; h < h1; h++) acc += r_w[h] * h_w[h*18 + o]; }
        else        { for (int h = h0; h < h1; h++) acc += r_w[h] * h_b[h]; }
        partial_s[t] = acc;
    } else if (t < 232) {
        fc_s[t - 152] = fc_w[t - 152];
    }
    __syncthreads();

    // S1/S2 decode is now valid for every thread.
    const int si = s64_s ? scand_s[1] : scand_s[0];
    const int sj = s64_s ? scand_s[3] : scand_s[2];

    // ---- Phase 1: weff reduce + (fast-path) 5x5 X patch, concurrently ----
    if (t >= 64 && t < 83) {
        int o = t - 64;
        float a = 0.0f;
        #pragma unroll
        for (int c = 0; c < 8; c++) a += partial_s[o*8 + c];
        weff_s[o] = a;
    }
    if (t < 50) {
        int c = t / 25, rr = (t % 25) / 5, cc = t % 5;
        int ii = si - 2 + rr, jj = sj - 2 + cc;
        xs_s[t] = (ii >= 0 && ii < 64 && jj >= 0 && jj < 64)
                  ? X[(size_t)b*8192 + c*4096 + ii*64 + jj] : 0.0f;
    }
    __syncthreads();

    if (!wnz_s) {
        // ================= FAST PATH (w == 0) =================
        if (t < 9) {
            int dy = t / 3, dx = t % 3;
            int ii = si - 1 + dy, jj = sj - 1 + dx;
            float vv = 0.0f;                        // SAME-pad zero for q conv
            if (ii >= 0 && ii < 64 && jj >= 0 && jj < 64) {
                float acc = weff_s[18];
                #pragma unroll
                for (int c = 0; c < 2; c++)
                    #pragma unroll
                    for (int ky = 0; ky < 3; ky++)
                        #pragma unroll
                        for (int kx = 0; kx < 3; kx++)
                            acc += weff_s[c*9 + ky*3 + kx]
                                 * xs_s[c*25 + (dy+ky)*5 + (dx+kx)];
                vv = acc;
            }
            rp_s[t] = vv;
        }
        __syncthreads();
        if (t < 10) {
            float acc = 0.0f;
            #pragma unroll
            for (int m = 0; m < 9; m++) acc += qw_s[t*9 + m] * rp_s[m];
            qv_s[t] = acc;
        }
        __syncthreads();
        if (t == 0) {
            float logits[8], lmax = -3.402823466e38f;
            #pragma unroll
            for (int j = 0; j < 8; j++) {
                float acc = 0.0f;
                #pragma unroll
                for (int a = 0; a < 10; a++) acc += qv_s[a] * fc_s[j*10 + a];
                logits[j] = acc;
                lmax = fmaxf(lmax, acc);
            }
            float ex[8], den = 0.0f;
            #pragma unroll
            for (int j = 0; j < 8; j++) { ex[j] = expf(logits[j] - lmax); den += ex[j]; }
            float inv = 1.0f / den;
            #pragma unroll
            for (int j = 0; j < 8; j++) {
                out[b*8 + j]          = logits[j];
                out[128*8 + b*8 + j]  = ex[j] * inv;
            }
        }
        return;
    }

    // ================= SLOW PATH (w != 0): full value iteration =================
    float* r_s  = sm + R_OFF;    // 66x68, zero halo; later v-next
    float* va_s = sm + VA_OFF;   // 66x68, zero halo
    float* qr_s = sm + QR_OFF;   // 10 x 64 x 64

    for (int idx = t; idx < 2*4488; idx += NT) sm[idx] = 0.0f;
    __syncthreads();

    // r = conv3x3(X, W_eff) + b_eff  (SAME)
    {
        float we[18];
        #pragma unroll
        for (int i2 = 0; i2 < 18; i2++) we[i2] = weff_s[i2];
        const float beff = weff_s[18];
        const float* X0 = X + (size_t)b * 8192;
        #pragma unroll 1
        for (int s = 0; s < 16; s++) {
            int p = s*NT + t;
            int i = p >> 6, j = p & 63;
            float acc = beff;
            #pragma unroll
            for (int c = 0; c < 2; c++) {
                const float* Xc = X0 + c*4096;
                #pragma unroll
                for (int dy = 0; dy < 3; dy++) {
                    int ii = i + dy - 1;
                    #pragma unroll
                    for (int dx = 0; dx < 3; dx++) {
                        int jj = j + dx - 1;
                        if (ii >= 0 && ii < 64 && jj >= 0 && jj < 64)
                            acc += we[c*9 + dy*3 + dx] * Xc[ii*64 + jj];
                    }
                }
            }
            r_s[(i+1)*PADW + (j+1)] = acc;
        }
    }
    __syncthreads();

    // qr[a] = conv3x3(r, q_w[a]); v0 = max_a qr
    {
        float qw[90];
        #pragma unroll
        for (int i2 = 0; i2 < 90; i2++) qw[i2] = qw_s[i2];
        #pragma unroll 1
        for (int s = 0; s < 16; s++) {
            int p = s*NT + t;
            int i = p >> 6, j = p & 63;
            float n[9];
            #pragma unroll
            for (int dy = 0; dy < 3; dy++)
                #pragma unroll
                for (int dx = 0; dx < 3; dx++)
                    n[dy*3 + dx] = r_s[(i+dy)*PADW + (j+dx)];
            float vmax = -3.402823466e38f;
            #pragma unroll
            for (int a = 0; a < 10; a++) {
                float acc = 0.0f;
                #pragma unroll
                for (int m = 0; m < 9; m++) acc += qw[a*9 + m] * n[m];
                qr_s[a*4096 + p] = acc;
                vmax = fmaxf(vmax, acc);
            }
            va_s[(i+1)*PADW + (j+1)] = vmax;
        }
    }
    __syncthreads();

    float ww[90];
    #pragma unroll
    for (int i2 = 0; i2 < 90; i2++) ww[i2] = ws[i2];

    float* vcur = va_s;
    float* vnxt = r_s;
    const int K = kval_s;
    for (int it = 0; it < K - 1; it++) {
        #pragma unroll 1
        for (int s = 0; s < 16; s++) {
            int p = s*NT + t;
            int i = p >> 6, j = p & 63;
            float n[9];
            #pragma unroll
            for (int dy = 0; dy < 3; dy++)
                #pragma unroll
                for (int dx = 0; dx < 3; dx++)
                    n[dy*3 + dx] = vcur[(i+dy)*PADW + (j+dx)];
            float vmax = -3.402823466e38f;
            #pragma unroll
            for (int a = 0; a < 10; a++) {
                float acc = qr_s[a*4096 + p];
                #pragma unroll
                for (int m = 0; m < 9; m++) acc += ww[a*9 + m] * n[m];
                vmax = fmaxf(vmax, acc);
            }
            vnxt[(i+1)*PADW + (j+1)] = vmax;
        }
        float* tmp = vcur; vcur = vnxt; vnxt = tmp;
        __syncthreads();
    }
    __syncthreads();

    if (t == 0) {
        float qout[10];
        #pragma unroll
        for (int a = 0; a < 10; a++) {
            float acc = qr_s[a*4096 + si*64 + sj];
            #pragma unroll
            for (int dy = 0; dy < 3; dy++)
                #pragma unroll
                for (int dx = 0; dx < 3; dx++)
                    acc += ww[a*9 + dy*3 + dx] * vcur[(si+dy)*PADW + (sj+dx)];
            qout[a] = acc;
        }
        float logits[8], lmax = -3.402823466e38f;
        #pragma unroll
        for (int j = 0; j < 8; j++) {
            float acc = 0.0f;
            #pragma unroll
            for (int a = 0; a < 10; a++) acc += qout[a] * fc_s[j*10 + a];
            logits[j] = acc;
            lmax = fmaxf(lmax, acc);
        }
        float ex[8], den = 0.0f;
        #pragma unroll
        for (int j = 0; j < 8; j++) { ex[j] = expf(logits[j] - lmax); den += ex[j]; }
        float inv = 1.0f / den;
        #pragma unroll
        for (int j = 0; j < 8; j++) {
            out[b*8 + j]          = logits[j];
            out[128*8 + b*8 + j]  = ex[j] * inv;
        }
    }
}

extern "C" void kernel_launch(void* const* d_in, const int* in_sizes, int n_in,
                              void* d_out, int out_size)
{
    (void)in_sizes; (void)out_size;
    const float* X    = (const float*)d_in[0];
    const float* h_w  = (const float*)d_in[1];
    const float* h_b  = (const float*)d_in[2];
    const float* r_w  = (const float*)d_in[3];
    const float* q_w  = (const float*)d_in[4];
    const float* w    = (const float*)d_in[5];
    const float* fc_w = (const float*)d_in[6];
    const void*  S1   = d_in[7];
    const void*  S2   = d_in[8];
    // d_in[9], d_in[10] = O1, O2: unused by the reference computation
    const void*  kv   = (n_in > 11) ? d_in[11] : nullptr;

    const size_t smem = SMEM_FLOATS * sizeof(float);   // ~199.7 KB (slow path)
    cudaFuncSetAttribute(vin_kernel, cudaFuncAttributeMaxDynamicSharedMemorySize, (int)smem);
    vin_kernel<<<128, NT, smem>>>(X, h_w, h_b, r_w, q_w, w, fc_w, S1, S2, kv,
                                  (float*)d_out);
}